// round 15
// baseline (speedup 1.0000x reference)
#include <cuda_runtime.h>
#include <cuda_fp16.h>
#include <stdint.h>
#include <math.h>

// Problem constants
#define B_   4096
#define T_   26
#define IN_  512
#define H_   512
#define NC_  97
#define NE_  256
#define K1_  (IN_ + NE_)   // 768  (x = concat(batch_H, emb))
#define KC_  (H_ + K1_)    // 1280 (combined [h | x] contraction)
#define G_   (4 * H_)      // 2048
#define M1_  (B_ * T_)     // 106496

// Recurrent kernel: A tile 128x(64k) = 16KB, B tile 256x(64k) = 32KB
#define TILE_A      16384
#define TILE_B      32768
#define RSTAGE      (TILE_A + TILE_B)        // 49152
#define NSTAGES     3
#define STAGEF_BYTES (128 * 132 * 4)         // 67584 (separate epilogue stage)
#define SMEM_REC    (NSTAGES * RSTAGE + STAGEF_BYTES + 128)  // ~215KB, occ 1

// probs kernel keeps the 128x128 shape (2x16KB stages)
#define PTILE       16384
#define PSTAGE      (2 * PTILE)
#define SMEM_PROBS  (NSTAGES * PSTAGE + 128)

// Persistent decomposition: 32 groups x 4 CTAs = 128 CTAs (<=148, occ 1)
#define GROUPS      32
#define GROUP_CTAS  4      // each CTA owns 512 n-cols = 2 passes of 256

// ---------------------------------------------------------------------------
// Scratch (device globals: no allocation allowed anywhere)
// ---------------------------------------------------------------------------
__device__ float g_c[B_ * H_];                    // cell state
__device__ __half g_x[(size_t)M1_ * K1_];         // concat(batch_H, emb) fp16
__device__ __half g_H[(size_t)M1_ * H_];          // hiddens fp16 [b*T+t, H]
__device__ __half g_W[G_ * KC_];                  // [Whh | Wih] fp16, gate-permuted
__device__ __half g_Wg[128 * H_];                 // W_gen padded to 128 rows
__device__ float g_bias[G_];                      // bih+bhh, PERMUTED gate order
__device__ int   g_bar[GROUPS];                   // per-group arrival counters

// ---------------------------------------------------------------------------
// PTX helpers (compute_103-safe: ldmatrix + mma.sync + cp.async)
// ---------------------------------------------------------------------------
__device__ __forceinline__ uint32_t smem_u32(const void* p) {
    uint32_t a;
    asm("{ .reg .u64 t; cvta.to.shared.u64 t, %1; cvt.u32.u64 %0, t; }"
        : "=r"(a) : "l"(p));
    return a;
}

__device__ __forceinline__ void ldmx4(uint32_t* r, uint32_t addr) {
    asm volatile("ldmatrix.sync.aligned.m8n8.x4.shared.b16 {%0,%1,%2,%3}, [%4];"
                 : "=r"(r[0]), "=r"(r[1]), "=r"(r[2]), "=r"(r[3]) : "r"(addr));
}

__device__ __forceinline__ void mma_f16(float* d, const uint32_t* a,
                                        uint32_t b0, uint32_t b1) {
    asm volatile(
        "mma.sync.aligned.m16n8k16.row.col.f32.f16.f16.f32 "
        "{%0,%1,%2,%3}, {%4,%5,%6,%7}, {%8,%9}, {%0,%1,%2,%3};"
        : "+f"(d[0]), "+f"(d[1]), "+f"(d[2]), "+f"(d[3])
        : "r"(a[0]), "r"(a[1]), "r"(a[2]), "r"(a[3]), "r"(b0), "r"(b1));
}

__device__ __forceinline__ void cp16(uint32_t s, const void* g) {
    asm volatile("cp.async.cg.shared.global [%0], [%1], 16;"
                 :: "r"(s), "l"(g) : "memory");
}
__device__ __forceinline__ void cp_commit() {
    asm volatile("cp.async.commit_group;" ::: "memory");
}
template <int N>
__device__ __forceinline__ void cp_wait() {
    asm volatile("cp.async.wait_group %0;" :: "n"(N) : "memory");
}

// fast pointwise (error ~2^-21; inf-safe)
__device__ __forceinline__ float fsig(float x) {
    return __fdividef(1.0f, 1.0f + __expf(-x));
}
__device__ __forceinline__ float ftanh(float x) {
    return 1.0f - __fdividef(2.0f, __expf(2.0f * x) + 1.0f);
}

// ---------------------------------------------------------------------------
// Small prep kernels
// ---------------------------------------------------------------------------
__global__ void zero_state_kernel() {
    int i = blockIdx.x * blockDim.x + threadIdx.x;
    ((float4*)g_c)[i] = make_float4(0.f, 0.f, 0.f, 0.f);
    if (blockIdx.x == 0 && threadIdx.x < GROUPS) g_bar[threadIdx.x] = 0;
}

// x = concat(batch_H, emb[text]) -> fp16.  grid = M1, block = 192
__global__ void convert_x_kernel(const float* __restrict__ bh,
                                 const int* __restrict__ text,
                                 const float* __restrict__ emb) {
    int m = blockIdx.x;
    int k = threadIdx.x * 4;
    float4 v;
    if (k < IN_) v = *(const float4*)(bh + (size_t)m * IN_ + k);
    else         v = *(const float4*)(emb + (size_t)text[m] * NE_ + (k - IN_));
    size_t o = (size_t)m * K1_ + k;
    g_x[o]   = __float2half_rn(v.x);
    g_x[o+1] = __float2half_rn(v.y);
    g_x[o+2] = __float2half_rn(v.z);
    g_x[o+3] = __float2half_rn(v.w);
}

// Combined weight [Whh | Wih], gate-permuted rows -> fp16.  grid = G_, block = 320
__global__ void convert_w_kernel(const float* __restrict__ Whh,
                                 const float* __restrict__ Wih) {
    int r = blockIdx.x;
    int k = threadIdx.x * 4;
    int sr = (r & 3) * H_ + (r >> 2);         // gate permutation
    float4 v;
    if (k < H_) v = *(const float4*)(Whh + (size_t)sr * H_ + k);
    else        v = *(const float4*)(Wih + (size_t)sr * K1_ + (k - H_));
    size_t o = (size_t)r * KC_ + k;
    g_W[o]   = __float2half_rn(v.x);
    g_W[o+1] = __float2half_rn(v.y);
    g_W[o+2] = __float2half_rn(v.z);
    g_W[o+3] = __float2half_rn(v.w);
}

// W_gen (padded to 128 rows) -> fp16.  grid = 128, block = 128
__global__ void convert_wg_kernel(const float* __restrict__ Wg) {
    int r = blockIdx.x;
    int k = threadIdx.x * 4;
    float4 v = make_float4(0.f, 0.f, 0.f, 0.f);
    if (r < NC_) v = *(const float4*)(Wg + (size_t)r * H_ + k);
    size_t o = (size_t)r * H_ + k;
    g_Wg[o]   = __float2half_rn(v.x);
    g_Wg[o+1] = __float2half_rn(v.y);
    g_Wg[o+2] = __float2half_rn(v.z);
    g_Wg[o+3] = __float2half_rn(v.w);
}

// g_bias[n] = bih[perm(n)] + bhh[perm(n)].  grid = 8, block = 256
__global__ void bias_kernel(const float* __restrict__ bih,
                            const float* __restrict__ bhh) {
    int n = blockIdx.x * blockDim.x + threadIdx.x;
    int sr = (n & 3) * H_ + (n >> 2);
    g_bias[n] = bih[sr] + bhh[sr];
}

// ---------------------------------------------------------------------------
// Persistent recurrent kernel: 128 CTAs = 32 groups x 4, occ 1.
// Group g owns batch rows [g*128, +128); CTA sub owns n-cols [sub*512, +512)
// as 2 passes of 256.  Warp tile 64x64 (8 warps).
// gates_t = [h_{t-1} | x_t] @ [Whh | Wih]^T, K = 1280.
// Chunk order per pass: 12 x-chunks FIRST, then 8 h-chunks (t=0: x only).
// A single linearized cp.async issue pointer runs 2 chunks ahead across all
// (step, pass) segments; the group-barrier WAIT is taken just before the
// first h-chunk load of each step, hiding barrier latency + producer skew
// behind ~10 chunks of x-compute.  ARRIVE right after the step epilogue.
// ---------------------------------------------------------------------------
__global__ void __launch_bounds__(256, 1)
recurrent_kernel(float* __restrict__ out_hid)
{
    extern __shared__ char dsm[];

    const int tid = threadIdx.x;
    const int wid = tid >> 5;
    const int lid = tid & 31;
    const int wm  = wid & 1;    // 2 m-blocks of 64
    const int wn  = wid >> 1;   // 4 n-blocks of 64
    const int grp = blockIdx.x >> 2;
    const int sub = blockIdx.x & 3;
    const int m0  = grp * 128;

    uint32_t raw  = smem_u32(dsm);
    uint32_t base = (raw + 127) & ~127u;
    uint32_t stg[NSTAGES];
#pragma unroll
    for (int s = 0; s < NSTAGES; s++) stg[s] = base + s * RSTAGE;
    float* stage_f = (float*)(dsm + (base - raw) + NSTAGES * RSTAGE);

    const int a_r  = lid & 15;
    const int a_kh = lid >> 4;
    const int b_r  = (lid & 7) + ((lid & 16) ? 8 : 0);
    const int b_kh = (lid >> 3) & 1;
    const int qr = lid >> 2, qc = lid & 3;

    // ---- linearized issue pointer ----
    int sp_i = 0, ci_i = 0, ring = 0;

    auto issue_one = [&]() {
        if (sp_i >= 2 * T_) { return; }          // stream exhausted
        const int tt  = sp_i >> 1;
        const int pp  = sp_i & 1;
        const int npp = sub * 512 + pp * 256;
        const int ci  = ci_i;
        const uint32_t sb = stg[ring % NSTAGES];
        const bool isx = (tt == 0) || (ci < 12);
        // A tile: 128 rows x 128B
#pragma unroll
        for (int i = tid; i < 1024; i += 256) {
            int r = i >> 3, u = i & 7;
            uint32_t sw = (r << 7) + ((u ^ (r & 7)) << 4);
            const __half* src = isx
                ? g_x + ((size_t)(m0 + r) * T_ + tt) * K1_ + ci * 64 + u * 8
                : g_H + ((size_t)(m0 + r) * T_ + (tt - 1)) * H_ + (ci - 12) * 64 + u * 8;
            cp16(sb + sw, src);
        }
        // B tile: 256 rows x 128B
        const int wk = isx ? (512 + ci * 64) : ((ci - 12) * 64);
#pragma unroll
        for (int i = tid; i < 2048; i += 256) {
            int r = i >> 3, u = i & 7;
            uint32_t sw = (r << 7) + ((u ^ (r & 7)) << 4);
            cp16(sb + TILE_A + sw, g_W + (size_t)(npp + r) * KC_ + wk + u * 8);
        }
        ring++;
        ci_i++;
        const int nchI = (sp_i < 2) ? 12 : 20;
        if (ci_i == nchI) { sp_i++; ci_i = 0; }
    };

    // wait for group's h(t-1) right before issuing the first h-chunk load
    auto maybe_wait = [&]() {
        if (sp_i < 2 * T_ && ci_i == 12 && (sp_i & 1) == 0) {
            const int tt = sp_i >> 1;    // >= 1 here (t=0 has no h chunks)
            if (tid == 0) {
                while (*(volatile int*)&g_bar[grp] < GROUP_CTAS * tt)
                    __nanosleep(64);
                __threadfence();
            }
            __syncthreads();
        }
    };

    // prologue: 2 chunks in flight
    maybe_wait(); issue_one(); cp_commit();
    maybe_wait(); issue_one(); cp_commit();

    int cons = 0;   // consume counter (stage = cons % 3)

    for (int sp = 0; sp < 2 * T_; sp++) {
        const int t    = sp >> 1;
        const int pass = sp & 1;
        const int np   = sub * 512 + pass * 256;
        const int nch  = (sp < 2) ? 12 : 20;

        float acc[4][8][4];
#pragma unroll
        for (int mt = 0; mt < 4; mt++)
#pragma unroll
            for (int nt = 0; nt < 8; nt++)
#pragma unroll
                for (int r = 0; r < 4; r++) acc[mt][nt][r] = 0.0f;

        for (int c = 0; c < nch; c++) {
            maybe_wait();
            issue_one();
            cp_commit();
            cp_wait<2>();
            __syncthreads();

            const uint32_t aA = stg[cons % NSTAGES];
            const uint32_t aB = aA + TILE_A;
            cons++;
#pragma unroll
            for (int ks = 0; ks < 4; ks++) {
                uint32_t af[4][4], bf[4][4];
#pragma unroll
                for (int mt = 0; mt < 4; mt++) {
                    int row = wm * 64 + mt * 16 + a_r;
                    int kb  = ks * 2 + a_kh;
                    ldmx4(af[mt], aA + (row << 7) + ((kb ^ (row & 7)) << 4));
                }
#pragma unroll
                for (int p = 0; p < 4; p++) {
                    int row = wn * 64 + p * 16 + b_r;
                    int kb  = ks * 2 + b_kh;
                    ldmx4(bf[p], aB + (row << 7) + ((kb ^ (row & 7)) << 4));
                }
#pragma unroll
                for (int mt = 0; mt < 4; mt++)
#pragma unroll
                    for (int nt = 0; nt < 8; nt++) {
                        int p = nt >> 1, o = (nt & 1) * 2;
                        mma_f16(acc[mt][nt], af[mt], bf[p][o], bf[p][o + 1]);
                    }
            }
            __syncthreads();
        }

        // ---- epilogue in two 128-col halves (stage_f is dedicated smem;
        //      prefetched pipeline stages stay untouched) ----
#pragma unroll 1
        for (int hf = 0; hf < 2; hf++) {
            if ((wn >> 1) == hf) {
#pragma unroll
                for (int mt = 0; mt < 4; mt++)
#pragma unroll
                    for (int nt = 0; nt < 8; nt++)
#pragma unroll
                        for (int half = 0; half < 2; half++) {
                            int r = wm * 64 + mt * 16 + qr + half * 8;
                            int n = (wn & 1) * 64 + nt * 8 + qc * 2;
                            stage_f[r * 132 + n]     = acc[mt][nt][half * 2];
                            stage_f[r * 132 + n + 1] = acc[mt][nt][half * 2 + 1];
                        }
            }
            __syncthreads();

            const int nb = np + hf * 128;   // global n-col base
            const int j0 = nb >> 2;         // first hidden unit
#pragma unroll
            for (int i = tid; i < 4096; i += 256) {
                int r  = i >> 5;
                int jj = i & 31;
                int b  = m0 + r;
                int j  = j0 + jj;
                float4 a4 = *(const float4*)&stage_f[r * 132 + jj * 4];
                float4 b4 = *(const float4*)(g_bias + nb + jj * 4);

                float i_ = fsig(a4.x + b4.x);
                float f_ = fsig(a4.y + b4.y);
                float g_ = ftanh(a4.z + b4.z);
                float o_ = fsig(a4.w + b4.w);

                int idx = b * H_ + j;
                float c = f_ * g_c[idx] + i_ * g_;
                float h = o_ * ftanh(c);
                g_c[idx] = c;

                size_t oo = ((size_t)b * T_ + t) * H_ + j;
                out_hid[oo] = h;
                g_H[oo]     = __float2half_rn(h);
            }
            __syncthreads();
        }

        // ---- arrive after the step's second pass (wait is elsewhere) ----
        if (pass == 1 && t + 1 < T_) {
            if (tid == 0) {
                __threadfence();
                atomicAdd(&g_bar[grp], 1);
            }
        }
    }
}

// ---------------------------------------------------------------------------
// probs GEMM: H @ Wgen^T, K=512 -> probs (+bg, n<97).  grid (1, 832), occ 2.
// ---------------------------------------------------------------------------
__global__ void __launch_bounds__(256, 2)
probs_kernel(const float* __restrict__ bias, float* __restrict__ outp)
{
    extern __shared__ char dsm[];

    const int tid = threadIdx.x;
    const int wid = tid >> 5;
    const int lid = tid & 31;
    const int wm  = wid & 1;
    const int wn  = wid >> 1;
    const int m0  = blockIdx.y * 128;

    uint32_t raw  = smem_u32(dsm);
    uint32_t base = (raw + 127) & ~127u;
    uint32_t stg[NSTAGES];
#pragma unroll
    for (int s = 0; s < NSTAGES; s++) stg[s] = base + s * PSTAGE;

    float acc[4][4][4];
#pragma unroll
    for (int mt = 0; mt < 4; mt++)
#pragma unroll
        for (int nt = 0; nt < 4; nt++)
#pragma unroll
            for (int r = 0; r < 4; r++) acc[mt][nt][r] = 0.0f;

    const int a_r  = lid & 15;
    const int a_kh = lid >> 4;
    const int b_r  = (lid & 7) + ((lid & 16) ? 8 : 0);
    const int b_kh = (lid >> 3) & 1;

    auto load_stage = [&](int ch, uint32_t sb) {
        const int k0 = ch * 64;
#pragma unroll
        for (int i = tid; i < 1024; i += 256) {
            int r = i >> 3, u = i & 7;
            uint32_t sw = (r << 7) + ((u ^ (r & 7)) << 4);
            cp16(sb + sw,         g_H  + (size_t)(m0 + r) * H_ + k0 + u * 8);
            cp16(sb + PTILE + sw, g_Wg + (size_t)r * H_ + k0 + u * 8);
        }
    };

    load_stage(0, stg[0]); cp_commit();
    load_stage(1, stg[1]); cp_commit();

    for (int ch = 0; ch < 8; ch++) {
        if (ch + 2 < 8) load_stage(ch + 2, stg[(ch + 2) % NSTAGES]);
        cp_commit();
        cp_wait<2>();
        __syncthreads();

        const uint32_t aA = stg[ch % NSTAGES];
        const uint32_t aB = aA + PTILE;
#pragma unroll
        for (int ks = 0; ks < 4; ks++) {
            uint32_t af[4][4], bf[2][4];
#pragma unroll
            for (int mt = 0; mt < 4; mt++) {
                int row = wm * 64 + mt * 16 + a_r;
                int kb  = ks * 2 + a_kh;
                ldmx4(af[mt], aA + (row << 7) + ((kb ^ (row & 7)) << 4));
            }
#pragma unroll
            for (int p = 0; p < 2; p++) {
                int row = wn * 32 + p * 16 + b_r;
                int kb  = ks * 2 + b_kh;
                ldmx4(bf[p], aB + (row << 7) + ((kb ^ (row & 7)) << 4));
            }
#pragma unroll
            for (int mt = 0; mt < 4; mt++)
#pragma unroll
                for (int nt = 0; nt < 4; nt++) {
                    int p = nt >> 1, o = (nt & 1) * 2;
                    mma_f16(acc[mt][nt], af[mt], bf[p][o], bf[p][o + 1]);
                }
        }
        __syncthreads();
    }

    const int qr = lid >> 2, qc = lid & 3;
#pragma unroll
    for (int mt = 0; mt < 4; mt++)
#pragma unroll
        for (int nt = 0; nt < 4; nt++)
#pragma unroll
            for (int half = 0; half < 2; half++) {
                int m = m0 + wm * 64 + mt * 16 + qr + half * 8;
                int n = wn * 32 + nt * 8 + qc * 2;
                float v0 = acc[mt][nt][half * 2];
                float v1 = acc[mt][nt][half * 2 + 1];
                if (n < NC_)     outp[(size_t)m * NC_ + n]     = v0 + bias[n];
                if (n + 1 < NC_) outp[(size_t)m * NC_ + n + 1] = v1 + bias[n + 1];
            }
}

// ---------------------------------------------------------------------------
// Launch: zero -> converts -> persistent recurrent (26 steps) -> probs
// d_out = [probs (B*T*97) | output_hiddens (B*T*512)]
// ---------------------------------------------------------------------------
extern "C" void kernel_launch(void* const* d_in, const int* in_sizes, int n_in,
                              void* d_out, int out_size)
{
    const float* bh   = (const float*)d_in[0];
    const int*   text = (const int*)  d_in[1];
    const float* emb  = (const float*)d_in[2];
    const float* Wih  = (const float*)d_in[3];
    const float* Whh  = (const float*)d_in[4];
    const float* bih  = (const float*)d_in[5];
    const float* bhh  = (const float*)d_in[6];
    const float* Wg   = (const float*)d_in[7];
    const float* bg   = (const float*)d_in[8];

    float* probs = (float*)d_out;                     // [M1, 97]
    float* hid   = probs + (size_t)M1_ * NC_;         // [M1, 512]

    (void)in_sizes; (void)n_in; (void)out_size;

    cudaFuncSetAttribute((const void*)recurrent_kernel,
                         cudaFuncAttributeMaxDynamicSharedMemorySize, SMEM_REC);
    cudaFuncSetAttribute((const void*)probs_kernel,
                         cudaFuncAttributeMaxDynamicSharedMemorySize, SMEM_PROBS);

    zero_state_kernel<<<(B_ * H_ / 4) / 256, 256>>>();
    convert_x_kernel<<<M1_, K1_ / 4>>>(bh, text, emb);
    convert_w_kernel<<<G_, KC_ / 4>>>(Whh, Wih);
    convert_wg_kernel<<<128, H_ / 4>>>(Wg);
    bias_kernel<<<8, 256>>>(bih, bhh);

    recurrent_kernel<<<GROUPS * GROUP_CTAS, 256, SMEM_REC>>>(hid);

    probs_kernel<<<dim3(1, 832), 256, SMEM_PROBS>>>(bg, probs);
}

// round 16
// speedup vs baseline: 1.1077x; 1.1077x over previous
#include <cuda_runtime.h>
#include <cuda_fp16.h>
#include <stdint.h>
#include <math.h>

// Problem constants
#define B_   4096
#define T_   26
#define IN_  512
#define H_   512
#define NC_  97
#define NE_  256
#define K1_  (IN_ + NE_)   // 768  (x = concat(batch_H, emb))
#define KC_  (H_ + K1_)    // 1280 (combined [h | x] contraction)
#define G_   (4 * H_)      // 2048
#define M1_  (B_ * T_)     // 106496

// Recurrent kernel: A tile 128x(64k) = 16KB, B tile 256x(64k) = 32KB
#define TILE_A      16384
#define TILE_B      32768
#define RSTAGE      (TILE_A + TILE_B)        // 49152
#define NSTAGES     3
#define SMEM_REC    (NSTAGES * RSTAGE + 128) // 147584 (occ 1)

// probs kernel keeps the 128x128 shape (2x16KB stages)
#define PTILE       16384
#define PSTAGE      (2 * PTILE)
#define SMEM_PROBS  (NSTAGES * PSTAGE + 128)

// Persistent decomposition: 32 groups x 4 CTAs = 128 CTAs (<=148, occ 1)
#define GROUPS      32
#define GROUP_CTAS  4      // each CTA owns 512 n-cols = 2 passes of 256

// ---------------------------------------------------------------------------
// Scratch (device globals: no allocation allowed anywhere)
// ---------------------------------------------------------------------------
__device__ float g_c[B_ * H_];                    // cell state
__device__ __half g_x[(size_t)M1_ * K1_];         // concat(batch_H, emb) fp16
__device__ __half g_H[(size_t)M1_ * H_];          // hiddens fp16 [b*T+t, H]
__device__ __half g_W[G_ * KC_];                  // [Whh | Wih] fp16, gate-permuted
__device__ __half g_Wg[128 * H_];                 // W_gen padded to 128 rows
__device__ float g_bias[G_];                      // bih+bhh, PERMUTED gate order
__device__ int   g_bar[GROUPS];                   // per-group arrival counters

// ---------------------------------------------------------------------------
// PTX helpers (compute_103-safe: ldmatrix + mma.sync + cp.async)
// ---------------------------------------------------------------------------
__device__ __forceinline__ uint32_t smem_u32(const void* p) {
    uint32_t a;
    asm("{ .reg .u64 t; cvta.to.shared.u64 t, %1; cvt.u32.u64 %0, t; }"
        : "=r"(a) : "l"(p));
    return a;
}

__device__ __forceinline__ void ldmx4(uint32_t* r, uint32_t addr) {
    asm volatile("ldmatrix.sync.aligned.m8n8.x4.shared.b16 {%0,%1,%2,%3}, [%4];"
                 : "=r"(r[0]), "=r"(r[1]), "=r"(r[2]), "=r"(r[3]) : "r"(addr));
}

__device__ __forceinline__ void mma_f16(float* d, const uint32_t* a,
                                        uint32_t b0, uint32_t b1) {
    asm volatile(
        "mma.sync.aligned.m16n8k16.row.col.f32.f16.f16.f32 "
        "{%0,%1,%2,%3}, {%4,%5,%6,%7}, {%8,%9}, {%0,%1,%2,%3};"
        : "+f"(d[0]), "+f"(d[1]), "+f"(d[2]), "+f"(d[3])
        : "r"(a[0]), "r"(a[1]), "r"(a[2]), "r"(a[3]), "r"(b0), "r"(b1));
}

__device__ __forceinline__ void cp16(uint32_t s, const void* g) {
    asm volatile("cp.async.cg.shared.global [%0], [%1], 16;"
                 :: "r"(s), "l"(g) : "memory");
}
__device__ __forceinline__ void cp_commit() {
    asm volatile("cp.async.commit_group;" ::: "memory");
}
template <int N>
__device__ __forceinline__ void cp_wait() {
    asm volatile("cp.async.wait_group %0;" :: "n"(N) : "memory");
}

// fast pointwise (error ~2^-21; inf-safe)
__device__ __forceinline__ float fsig(float x) {
    return __fdividef(1.0f, 1.0f + __expf(-x));
}
__device__ __forceinline__ float ftanh(float x) {
    return 1.0f - __fdividef(2.0f, __expf(2.0f * x) + 1.0f);
}

// ---------------------------------------------------------------------------
// Small prep kernels
// ---------------------------------------------------------------------------
__global__ void zero_state_kernel() {
    int i = blockIdx.x * blockDim.x + threadIdx.x;
    ((float4*)g_c)[i] = make_float4(0.f, 0.f, 0.f, 0.f);
    if (blockIdx.x == 0 && threadIdx.x < GROUPS) g_bar[threadIdx.x] = 0;
}

// x = concat(batch_H, emb[text]) -> fp16.  grid = M1, block = 192
__global__ void convert_x_kernel(const float* __restrict__ bh,
                                 const int* __restrict__ text,
                                 const float* __restrict__ emb) {
    int m = blockIdx.x;
    int k = threadIdx.x * 4;
    float4 v;
    if (k < IN_) v = *(const float4*)(bh + (size_t)m * IN_ + k);
    else         v = *(const float4*)(emb + (size_t)text[m] * NE_ + (k - IN_));
    size_t o = (size_t)m * K1_ + k;
    g_x[o]   = __float2half_rn(v.x);
    g_x[o+1] = __float2half_rn(v.y);
    g_x[o+2] = __float2half_rn(v.z);
    g_x[o+3] = __float2half_rn(v.w);
}

// Combined weight [Whh | Wih], gate-permuted rows -> fp16.  grid = G_, block = 320
__global__ void convert_w_kernel(const float* __restrict__ Whh,
                                 const float* __restrict__ Wih) {
    int r = blockIdx.x;
    int k = threadIdx.x * 4;
    int sr = (r & 3) * H_ + (r >> 2);         // gate permutation
    float4 v;
    if (k < H_) v = *(const float4*)(Whh + (size_t)sr * H_ + k);
    else        v = *(const float4*)(Wih + (size_t)sr * K1_ + (k - H_));
    size_t o = (size_t)r * KC_ + k;
    g_W[o]   = __float2half_rn(v.x);
    g_W[o+1] = __float2half_rn(v.y);
    g_W[o+2] = __float2half_rn(v.z);
    g_W[o+3] = __float2half_rn(v.w);
}

// W_gen (padded to 128 rows) -> fp16.  grid = 128, block = 128
__global__ void convert_wg_kernel(const float* __restrict__ Wg) {
    int r = blockIdx.x;
    int k = threadIdx.x * 4;
    float4 v = make_float4(0.f, 0.f, 0.f, 0.f);
    if (r < NC_) v = *(const float4*)(Wg + (size_t)r * H_ + k);
    size_t o = (size_t)r * H_ + k;
    g_Wg[o]   = __float2half_rn(v.x);
    g_Wg[o+1] = __float2half_rn(v.y);
    g_Wg[o+2] = __float2half_rn(v.z);
    g_Wg[o+3] = __float2half_rn(v.w);
}

// g_bias[n] = bih[perm(n)] + bhh[perm(n)].  grid = 8, block = 256
__global__ void bias_kernel(const float* __restrict__ bih,
                            const float* __restrict__ bhh) {
    int n = blockIdx.x * blockDim.x + threadIdx.x;
    int sr = (n & 3) * H_ + (n >> 2);
    g_bias[n] = bih[sr] + bhh[sr];
}

// ---------------------------------------------------------------------------
// Persistent recurrent kernel: 128 CTAs = 32 groups x 4, occ 1.
// Group g owns batch rows [g*128, +128); CTA sub owns n-cols [sub*512, +512)
// as 2 passes of 256.  Warp tile 64x64 (8 warps).
// gates_t = [h_{t-1} | x_t] @ [Whh | Wih]^T, K = 1280 (20 chunks of 64).
// Chunk order per pass: 12 x-chunks FIRST (ch 0..11), then 8 h-chunks
// (ch 12..19).  t=0 runs only the 12 x-chunks (h = 0).
// Group-barrier WAIT happens in pass 0 at ch==10 — just before the first
// h-chunk prefetch — hiding barrier latency + producer skew behind the
// x-chunk compute.  ARRIVE after the step's pass-1 epilogue.
// ---------------------------------------------------------------------------
__global__ void __launch_bounds__(256, 1)
recurrent_kernel(float* __restrict__ out_hid)
{
    extern __shared__ char dsm[];

    const int tid = threadIdx.x;
    const int wid = tid >> 5;
    const int lid = tid & 31;
    const int wm  = wid & 1;    // 2 m-blocks of 64
    const int wn  = wid >> 1;   // 4 n-blocks of 64
    const int grp = blockIdx.x >> 2;
    const int sub = blockIdx.x & 3;
    const int m0  = grp * 128;

    uint32_t raw  = smem_u32(dsm);
    uint32_t base = (raw + 127) & ~127u;
    float* stage_f = (float*)(dsm + (base - raw));   // 128x132 f32 (epilogue)
    uint32_t stg[NSTAGES];
#pragma unroll
    for (int s = 0; s < NSTAGES; s++) stg[s] = base + s * RSTAGE;

    const int a_r  = lid & 15;
    const int a_kh = lid >> 4;
    const int b_r  = (lid & 7) + ((lid & 16) ? 8 : 0);
    const int b_kh = (lid >> 3) & 1;
    const int qr = lid >> 2, qc = lid & 3;

    for (int t = 0; t < T_; t++) {
        const int nch = (t == 0) ? 12 : 20;   // t=0: x-chunks only

#pragma unroll 1
        for (int pass = 0; pass < 2; pass++) {
            const int np = sub * 512 + pass * 256;      // 256 n-cols this pass

            float acc[4][8][4];
#pragma unroll
            for (int mt = 0; mt < 4; mt++)
#pragma unroll
                for (int nt = 0; nt < 8; nt++)
#pragma unroll
                    for (int r = 0; r < 4; r++) acc[mt][nt][r] = 0.0f;

            // chunk ch: 0..11 -> x(t) (W cols 512+ch*64), 12..19 -> h(t-1)
            auto load_stage = [&](int ch, uint32_t sb) {
                const bool isx = (ch < 12);
                // A: 128 rows x 128B
#pragma unroll
                for (int i = tid; i < 1024; i += 256) {
                    int r = i >> 3, u = i & 7;
                    uint32_t sw = (r << 7) + ((u ^ (r & 7)) << 4);
                    const __half* src = isx
                        ? g_x + ((size_t)(m0 + r) * T_ + t) * K1_ + ch * 64 + u * 8
                        : g_H + ((size_t)(m0 + r) * T_ + (t - 1)) * H_ + (ch - 12) * 64 + u * 8;
                    cp16(sb + sw, src);
                }
                // B: 256 rows x 128B
                const int wk = isx ? (512 + ch * 64) : ((ch - 12) * 64);
#pragma unroll
                for (int i = tid; i < 2048; i += 256) {
                    int r = i >> 3, u = i & 7;
                    uint32_t sw = (r << 7) + ((u ^ (r & 7)) << 4);
                    cp16(sb + TILE_A + sw,
                         g_W + (size_t)(np + r) * KC_ + wk + u * 8);
                }
            };

            load_stage(0, stg[0]); cp_commit();
            load_stage(1, stg[1]); cp_commit();

            for (int ch = 0; ch < nch; ch++) {
                // hide group-barrier wait behind the x-chunk compute:
                // wait just before prefetching the first h-chunk (ch+2 == 12)
                if (pass == 0 && t > 0 && ch == 10) {
                    if (tid == 0) {
                        while (*(volatile int*)&g_bar[grp] < GROUP_CTAS * t)
                            __nanosleep(64);
                        __threadfence();
                    }
                    __syncthreads();
                }
                if (ch + 2 < nch) load_stage(ch + 2, stg[(ch + 2) % NSTAGES]);
                cp_commit();
                cp_wait<2>();
                __syncthreads();

                const uint32_t aA = stg[ch % NSTAGES];
                const uint32_t aB = aA + TILE_A;
#pragma unroll
                for (int ks = 0; ks < 4; ks++) {
                    uint32_t af[4][4], bf[4][4];
#pragma unroll
                    for (int mt = 0; mt < 4; mt++) {
                        int row = wm * 64 + mt * 16 + a_r;
                        int kb  = ks * 2 + a_kh;
                        ldmx4(af[mt], aA + (row << 7) + ((kb ^ (row & 7)) << 4));
                    }
#pragma unroll
                    for (int p = 0; p < 4; p++) {
                        int row = wn * 64 + p * 16 + b_r;
                        int kb  = ks * 2 + b_kh;
                        ldmx4(bf[p], aB + (row << 7) + ((kb ^ (row & 7)) << 4));
                    }
#pragma unroll
                    for (int mt = 0; mt < 4; mt++)
#pragma unroll
                        for (int nt = 0; nt < 8; nt++) {
                            int p = nt >> 1, o = (nt & 1) * 2;
                            mma_f16(acc[mt][nt], af[mt], bf[p][o], bf[p][o + 1]);
                        }
                }
                __syncthreads();
            }
            cp_wait<0>();
            __syncthreads();   // all async writes done before stage_f reuse

            // ---- epilogue in two 128-col halves ----
#pragma unroll 1
            for (int hf = 0; hf < 2; hf++) {
                if ((wn >> 1) == hf) {
#pragma unroll
                    for (int mt = 0; mt < 4; mt++)
#pragma unroll
                        for (int nt = 0; nt < 8; nt++)
#pragma unroll
                            for (int half = 0; half < 2; half++) {
                                int r = wm * 64 + mt * 16 + qr + half * 8;
                                int n = (wn & 1) * 64 + nt * 8 + qc * 2;
                                stage_f[r * 132 + n]     = acc[mt][nt][half * 2];
                                stage_f[r * 132 + n + 1] = acc[mt][nt][half * 2 + 1];
                            }
                }
                __syncthreads();

                const int nb = np + hf * 128;   // global n-col base
                const int j0 = nb >> 2;         // first hidden unit
#pragma unroll
                for (int i = tid; i < 4096; i += 256) {
                    int r  = i >> 5;
                    int jj = i & 31;
                    int b  = m0 + r;
                    int j  = j0 + jj;
                    float4 a4 = *(const float4*)&stage_f[r * 132 + jj * 4];
                    float4 b4 = *(const float4*)(g_bias + nb + jj * 4);

                    float i_ = fsig(a4.x + b4.x);
                    float f_ = fsig(a4.y + b4.y);
                    float g_ = ftanh(a4.z + b4.z);
                    float o_ = fsig(a4.w + b4.w);

                    int idx = b * H_ + j;
                    float c = f_ * g_c[idx] + i_ * g_;
                    float h = o_ * ftanh(c);
                    g_c[idx] = c;

                    size_t oo = ((size_t)b * T_ + t) * H_ + j;
                    out_hid[oo] = h;
                    g_H[oo]     = __float2half_rn(h);
                }
                __syncthreads();
            }
        }

        // ---- arrive after the step's second pass (wait is inside pass 0) ----
        if (t + 1 < T_) {
            if (tid == 0) {
                __threadfence();
                atomicAdd(&g_bar[grp], 1);
            }
            __syncthreads();
        }
    }
}

// ---------------------------------------------------------------------------
// probs GEMM: H @ Wgen^T, K=512 -> probs (+bg, n<97).  grid (1, 832), occ 2.
// ---------------------------------------------------------------------------
__global__ void __launch_bounds__(256, 2)
probs_kernel(const float* __restrict__ bias, float* __restrict__ outp)
{
    extern __shared__ char dsm[];

    const int tid = threadIdx.x;
    const int wid = tid >> 5;
    const int lid = tid & 31;
    const int wm  = wid & 1;
    const int wn  = wid >> 1;
    const int m0  = blockIdx.y * 128;

    uint32_t raw  = smem_u32(dsm);
    uint32_t base = (raw + 127) & ~127u;
    uint32_t stg[NSTAGES];
#pragma unroll
    for (int s = 0; s < NSTAGES; s++) stg[s] = base + s * PSTAGE;

    float acc[4][4][4];
#pragma unroll
    for (int mt = 0; mt < 4; mt++)
#pragma unroll
        for (int nt = 0; nt < 4; nt++)
#pragma unroll
            for (int r = 0; r < 4; r++) acc[mt][nt][r] = 0.0f;

    const int a_r  = lid & 15;
    const int a_kh = lid >> 4;
    const int b_r  = (lid & 7) + ((lid & 16) ? 8 : 0);
    const int b_kh = (lid >> 3) & 1;

    auto load_stage = [&](int ch, uint32_t sb) {
        const int k0 = ch * 64;
#pragma unroll
        for (int i = tid; i < 1024; i += 256) {
            int r = i >> 3, u = i & 7;
            uint32_t sw = (r << 7) + ((u ^ (r & 7)) << 4);
            cp16(sb + sw,         g_H  + (size_t)(m0 + r) * H_ + k0 + u * 8);
            cp16(sb + PTILE + sw, g_Wg + (size_t)r * H_ + k0 + u * 8);
        }
    };

    load_stage(0, stg[0]); cp_commit();
    load_stage(1, stg[1]); cp_commit();

    for (int ch = 0; ch < 8; ch++) {
        if (ch + 2 < 8) load_stage(ch + 2, stg[(ch + 2) % NSTAGES]);
        cp_commit();
        cp_wait<2>();
        __syncthreads();

        const uint32_t aA = stg[ch % NSTAGES];
        const uint32_t aB = aA + PTILE;
#pragma unroll
        for (int ks = 0; ks < 4; ks++) {
            uint32_t af[4][4], bf[2][4];
#pragma unroll
            for (int mt = 0; mt < 4; mt++) {
                int row = wm * 64 + mt * 16 + a_r;
                int kb  = ks * 2 + a_kh;
                ldmx4(af[mt], aA + (row << 7) + ((kb ^ (row & 7)) << 4));
            }
#pragma unroll
            for (int p = 0; p < 2; p++) {
                int row = wn * 32 + p * 16 + b_r;
                int kb  = ks * 2 + b_kh;
                ldmx4(bf[p], aB + (row << 7) + ((kb ^ (row & 7)) << 4));
            }
#pragma unroll
            for (int mt = 0; mt < 4; mt++)
#pragma unroll
                for (int nt = 0; nt < 4; nt++) {
                    int p = nt >> 1, o = (nt & 1) * 2;
                    mma_f16(acc[mt][nt], af[mt], bf[p][o], bf[p][o + 1]);
                }
        }
        __syncthreads();
    }

    const int qr = lid >> 2, qc = lid & 3;
#pragma unroll
    for (int mt = 0; mt < 4; mt++)
#pragma unroll
        for (int nt = 0; nt < 4; nt++)
#pragma unroll
            for (int half = 0; half < 2; half++) {
                int m = m0 + wm * 64 + mt * 16 + qr + half * 8;
                int n = wn * 32 + nt * 8 + qc * 2;
                float v0 = acc[mt][nt][half * 2];
                float v1 = acc[mt][nt][half * 2 + 1];
                if (n < NC_)     outp[(size_t)m * NC_ + n]     = v0 + bias[n];
                if (n + 1 < NC_) outp[(size_t)m * NC_ + n + 1] = v1 + bias[n + 1];
            }
}

// ---------------------------------------------------------------------------
// Launch: zero -> converts -> persistent recurrent (26 steps) -> probs
// d_out = [probs (B*T*97) | output_hiddens (B*T*512)]
// ---------------------------------------------------------------------------
extern "C" void kernel_launch(void* const* d_in, const int* in_sizes, int n_in,
                              void* d_out, int out_size)
{
    const float* bh   = (const float*)d_in[0];
    const int*   text = (const int*)  d_in[1];
    const float* emb  = (const float*)d_in[2];
    const float* Wih  = (const float*)d_in[3];
    const float* Whh  = (const float*)d_in[4];
    const float* bih  = (const float*)d_in[5];
    const float* bhh  = (const float*)d_in[6];
    const float* Wg   = (const float*)d_in[7];
    const float* bg   = (const float*)d_in[8];

    float* probs = (float*)d_out;                     // [M1, 97]
    float* hid   = probs + (size_t)M1_ * NC_;         // [M1, 512]

    (void)in_sizes; (void)n_in; (void)out_size;

    cudaFuncSetAttribute((const void*)recurrent_kernel,
                         cudaFuncAttributeMaxDynamicSharedMemorySize, SMEM_REC);
    cudaFuncSetAttribute((const void*)probs_kernel,
                         cudaFuncAttributeMaxDynamicSharedMemorySize, SMEM_PROBS);

    zero_state_kernel<<<(B_ * H_ / 4) / 256, 256>>>();
    convert_x_kernel<<<M1_, K1_ / 4>>>(bh, text, emb);
    convert_w_kernel<<<G_, KC_ / 4>>>(Whh, Wih);
    convert_wg_kernel<<<128, H_ / 4>>>(Wg);
    bias_kernel<<<8, 256>>>(bih, bhh);

    recurrent_kernel<<<GROUPS * GROUP_CTAS, 256, SMEM_REC>>>(hid);

    probs_kernel<<<dim3(1, 832), 256, SMEM_PROBS>>>(bg, probs);
}

// round 17
// speedup vs baseline: 1.1456x; 1.0343x over previous
#include <cuda_runtime.h>
#include <cuda_fp16.h>
#include <stdint.h>
#include <math.h>

// Problem constants
#define B_   4096
#define T_   26
#define IN_  512
#define H_   512
#define NC_  97
#define NE_  256
#define K1_  (IN_ + NE_)   // 768  (x = concat(batch_H, emb))
#define KC_  (H_ + K1_)    // 1280 (combined [h | x] contraction)
#define G_   (4 * H_)      // 2048
#define M1_  (B_ * T_)     // 106496

// Recurrent kernel: A tile 128x(64k) = 16KB, B tile 256x(64k) = 32KB
#define TILE_A      16384
#define TILE_B      32768
#define RSTAGE      (TILE_A + TILE_B)        // 49152
#define RNSTAGES    4                        // 4 stages -> drop trailing sync
#define SMEM_REC    (RNSTAGES * RSTAGE + 128)   // 196736 (occ 1)
#define STF_W       264                      // epilogue stage row stride (floats)

// probs kernel keeps the 128x128 shape (3 x 2x16KB stages)
#define PTILE       16384
#define PSTAGE      (2 * PTILE)
#define PNSTAGES    3
#define SMEM_PROBS  (PNSTAGES * PSTAGE + 128)

// Persistent decomposition: 32 groups x 4 CTAs = 128 CTAs (<=148, occ 1)
#define GROUPS      32
#define GROUP_CTAS  4      // each CTA owns 512 n-cols = 2 passes of 256

// ---------------------------------------------------------------------------
// Scratch (device globals: no allocation allowed anywhere)
// ---------------------------------------------------------------------------
__device__ float g_c[B_ * H_];                    // cell state
__device__ __half g_x[(size_t)M1_ * K1_];         // concat(batch_H, emb) fp16
__device__ __half g_H[(size_t)M1_ * H_];          // hiddens fp16 [b*T+t, H]
__device__ __half g_W[G_ * KC_];                  // [Whh | Wih] fp16, gate-permuted
__device__ __half g_Wg[128 * H_];                 // W_gen padded to 128 rows
__device__ float g_bias[G_];                      // bih+bhh, PERMUTED gate order
__device__ int   g_bar[GROUPS];                   // per-group arrival counters

// ---------------------------------------------------------------------------
// PTX helpers (compute_103-safe: ldmatrix + mma.sync + cp.async)
// ---------------------------------------------------------------------------
__device__ __forceinline__ uint32_t smem_u32(const void* p) {
    uint32_t a;
    asm("{ .reg .u64 t; cvta.to.shared.u64 t, %1; cvt.u32.u64 %0, t; }"
        : "=r"(a) : "l"(p));
    return a;
}

__device__ __forceinline__ void ldmx4(uint32_t* r, uint32_t addr) {
    asm volatile("ldmatrix.sync.aligned.m8n8.x4.shared.b16 {%0,%1,%2,%3}, [%4];"
                 : "=r"(r[0]), "=r"(r[1]), "=r"(r[2]), "=r"(r[3]) : "r"(addr));
}

__device__ __forceinline__ void mma_f16(float* d, const uint32_t* a,
                                        uint32_t b0, uint32_t b1) {
    asm volatile(
        "mma.sync.aligned.m16n8k16.row.col.f32.f16.f16.f32 "
        "{%0,%1,%2,%3}, {%4,%5,%6,%7}, {%8,%9}, {%0,%1,%2,%3};"
        : "+f"(d[0]), "+f"(d[1]), "+f"(d[2]), "+f"(d[3])
        : "r"(a[0]), "r"(a[1]), "r"(a[2]), "r"(a[3]), "r"(b0), "r"(b1));
}

__device__ __forceinline__ void cp16(uint32_t s, const void* g) {
    asm volatile("cp.async.cg.shared.global [%0], [%1], 16;"
                 :: "r"(s), "l"(g) : "memory");
}
__device__ __forceinline__ void cp_commit() {
    asm volatile("cp.async.commit_group;" ::: "memory");
}
template <int N>
__device__ __forceinline__ void cp_wait() {
    asm volatile("cp.async.wait_group %0;" :: "n"(N) : "memory");
}

// fast pointwise (error ~2^-21; inf-safe)
__device__ __forceinline__ float fsig(float x) {
    return __fdividef(1.0f, 1.0f + __expf(-x));
}
__device__ __forceinline__ float ftanh(float x) {
    return 1.0f - __fdividef(2.0f, __expf(2.0f * x) + 1.0f);
}

// ---------------------------------------------------------------------------
// Small prep kernels
// ---------------------------------------------------------------------------
__global__ void zero_state_kernel() {
    int i = blockIdx.x * blockDim.x + threadIdx.x;
    ((float4*)g_c)[i] = make_float4(0.f, 0.f, 0.f, 0.f);
    if (blockIdx.x == 0 && threadIdx.x < GROUPS) g_bar[threadIdx.x] = 0;
}

// x = concat(batch_H, emb[text]) -> fp16.  grid = M1, block = 192
__global__ void convert_x_kernel(const float* __restrict__ bh,
                                 const int* __restrict__ text,
                                 const float* __restrict__ emb) {
    int m = blockIdx.x;
    int k = threadIdx.x * 4;
    float4 v;
    if (k < IN_) v = *(const float4*)(bh + (size_t)m * IN_ + k);
    else         v = *(const float4*)(emb + (size_t)text[m] * NE_ + (k - IN_));
    size_t o = (size_t)m * K1_ + k;
    g_x[o]   = __float2half_rn(v.x);
    g_x[o+1] = __float2half_rn(v.y);
    g_x[o+2] = __float2half_rn(v.z);
    g_x[o+3] = __float2half_rn(v.w);
}

// Combined weight [Whh | Wih], gate-permuted rows -> fp16.  grid = G_, block = 320
__global__ void convert_w_kernel(const float* __restrict__ Whh,
                                 const float* __restrict__ Wih) {
    int r = blockIdx.x;
    int k = threadIdx.x * 4;
    int sr = (r & 3) * H_ + (r >> 2);         // gate permutation
    float4 v;
    if (k < H_) v = *(const float4*)(Whh + (size_t)sr * H_ + k);
    else        v = *(const float4*)(Wih + (size_t)sr * K1_ + (k - H_));
    size_t o = (size_t)r * KC_ + k;
    g_W[o]   = __float2half_rn(v.x);
    g_W[o+1] = __float2half_rn(v.y);
    g_W[o+2] = __float2half_rn(v.z);
    g_W[o+3] = __float2half_rn(v.w);
}

// W_gen (padded to 128 rows) -> fp16.  grid = 128, block = 128
__global__ void convert_wg_kernel(const float* __restrict__ Wg) {
    int r = blockIdx.x;
    int k = threadIdx.x * 4;
    float4 v = make_float4(0.f, 0.f, 0.f, 0.f);
    if (r < NC_) v = *(const float4*)(Wg + (size_t)r * H_ + k);
    size_t o = (size_t)r * H_ + k;
    g_Wg[o]   = __float2half_rn(v.x);
    g_Wg[o+1] = __float2half_rn(v.y);
    g_Wg[o+2] = __float2half_rn(v.z);
    g_Wg[o+3] = __float2half_rn(v.w);
}

// g_bias[n] = bih[perm(n)] + bhh[perm(n)].  grid = 8, block = 256
__global__ void bias_kernel(const float* __restrict__ bih,
                            const float* __restrict__ bhh) {
    int n = blockIdx.x * blockDim.x + threadIdx.x;
    int sr = (n & 3) * H_ + (n >> 2);
    g_bias[n] = bih[sr] + bhh[sr];
}

// ---------------------------------------------------------------------------
// Persistent recurrent kernel: 128 CTAs = 32 groups x 4, occ 1.
// Group g owns batch rows [g*128, +128); CTA sub owns n-cols [sub*512, +512)
// as 2 passes of 256.  Warp tile 64x64 (8 warps).
// gates_t = [h_{t-1} | x_t] @ [Whh | Wih]^T, K = 1280 (20 chunks of 64).
// Chunk order per pass: 12 x-chunks FIRST (ch 0..11), then 8 h-chunks
// (ch 12..19).  t=0 runs only the 12 x-chunks (h = 0).
// 4 smem stages + prefetch distance 2 => ONE __syncthreads per chunk
// (write stage (ch+2)%4 can never collide with an adjacent iteration's
// reads).  Group-barrier WAIT hidden at ch==10; ARRIVE after the step.
// Epilogue: single-shot full-width 128x264 f32 stage (aliases pipe smem).
// ---------------------------------------------------------------------------
__global__ void __launch_bounds__(256, 1)
recurrent_kernel(float* __restrict__ out_hid)
{
    extern __shared__ char dsm[];

    const int tid = threadIdx.x;
    const int wid = tid >> 5;
    const int lid = tid & 31;
    const int wm  = wid & 1;    // 2 m-blocks of 64
    const int wn  = wid >> 1;   // 4 n-blocks of 64
    const int grp = blockIdx.x >> 2;
    const int sub = blockIdx.x & 3;
    const int m0  = grp * 128;

    uint32_t raw  = smem_u32(dsm);
    uint32_t base = (raw + 127) & ~127u;
    float* stage_f = (float*)(dsm + (base - raw));   // 128x264 f32 (epilogue)
    uint32_t stg[RNSTAGES];
#pragma unroll
    for (int s = 0; s < RNSTAGES; s++) stg[s] = base + s * RSTAGE;

    const int a_r  = lid & 15;
    const int a_kh = lid >> 4;
    const int b_r  = (lid & 7) + ((lid & 16) ? 8 : 0);
    const int b_kh = (lid >> 3) & 1;
    const int qr = lid >> 2, qc = lid & 3;

    for (int t = 0; t < T_; t++) {
        const int nch = (t == 0) ? 12 : 20;   // t=0: x-chunks only

#pragma unroll 1
        for (int pass = 0; pass < 2; pass++) {
            const int np = sub * 512 + pass * 256;      // 256 n-cols this pass

            float acc[4][8][4];
#pragma unroll
            for (int mt = 0; mt < 4; mt++)
#pragma unroll
                for (int nt = 0; nt < 8; nt++)
#pragma unroll
                    for (int r = 0; r < 4; r++) acc[mt][nt][r] = 0.0f;

            // chunk ch: 0..11 -> x(t) (W cols 512+ch*64), 12..19 -> h(t-1)
            auto load_stage = [&](int ch, uint32_t sb) {
                const bool isx = (ch < 12);
                // A: 128 rows x 128B
#pragma unroll
                for (int i = tid; i < 1024; i += 256) {
                    int r = i >> 3, u = i & 7;
                    uint32_t sw = (r << 7) + ((u ^ (r & 7)) << 4);
                    const __half* src = isx
                        ? g_x + ((size_t)(m0 + r) * T_ + t) * K1_ + ch * 64 + u * 8
                        : g_H + ((size_t)(m0 + r) * T_ + (t - 1)) * H_ + (ch - 12) * 64 + u * 8;
                    cp16(sb + sw, src);
                }
                // B: 256 rows x 128B
                const int wk = isx ? (512 + ch * 64) : ((ch - 12) * 64);
#pragma unroll
                for (int i = tid; i < 2048; i += 256) {
                    int r = i >> 3, u = i & 7;
                    uint32_t sw = (r << 7) + ((u ^ (r & 7)) << 4);
                    cp16(sb + TILE_A + sw,
                         g_W + (size_t)(np + r) * KC_ + wk + u * 8);
                }
            };

            load_stage(0, stg[0]); cp_commit();
            load_stage(1, stg[1]); cp_commit();

            for (int ch = 0; ch < nch; ch++) {
                // hide group-barrier wait behind the x-chunk compute:
                // wait just before prefetching the first h-chunk (ch+2 == 12)
                if (pass == 0 && t > 0 && ch == 10) {
                    if (tid == 0) {
                        while (*(volatile int*)&g_bar[grp] < GROUP_CTAS * t)
                            __nanosleep(64);
                        __threadfence();
                    }
                    __syncthreads();
                }
                if (ch + 2 < nch) load_stage(ch + 2, stg[(ch + 2) % RNSTAGES]);
                cp_commit();
                cp_wait<2>();
                __syncthreads();

                const uint32_t aA = stg[ch % RNSTAGES];
                const uint32_t aB = aA + TILE_A;
#pragma unroll
                for (int ks = 0; ks < 4; ks++) {
                    uint32_t af[4][4], bf[4][4];
#pragma unroll
                    for (int mt = 0; mt < 4; mt++) {
                        int row = wm * 64 + mt * 16 + a_r;
                        int kb  = ks * 2 + a_kh;
                        ldmx4(af[mt], aA + (row << 7) + ((kb ^ (row & 7)) << 4));
                    }
#pragma unroll
                    for (int p = 0; p < 4; p++) {
                        int row = wn * 64 + p * 16 + b_r;
                        int kb  = ks * 2 + b_kh;
                        ldmx4(bf[p], aB + (row << 7) + ((kb ^ (row & 7)) << 4));
                    }
#pragma unroll
                    for (int mt = 0; mt < 4; mt++)
#pragma unroll
                        for (int nt = 0; nt < 8; nt++) {
                            int p = nt >> 1, o = (nt & 1) * 2;
                            mma_f16(acc[mt][nt], af[mt], bf[p][o], bf[p][o + 1]);
                        }
                }
                // no trailing __syncthreads: 4 stages + distance-2 prefetch
                // => next iteration's writes never touch a stage readable by
                // an adjacent-iteration warp.
            }
            cp_wait<0>();
            __syncthreads();   // all async writes done before stage_f reuse

            // ---- single-shot epilogue: all 256 cols at once ----
#pragma unroll
            for (int mt = 0; mt < 4; mt++)
#pragma unroll
                for (int nt = 0; nt < 8; nt++)
#pragma unroll
                    for (int half = 0; half < 2; half++) {
                        int r = wm * 64 + mt * 16 + qr + half * 8;
                        int n = wn * 64 + nt * 8 + qc * 2;
                        stage_f[r * STF_W + n]     = acc[mt][nt][half * 2];
                        stage_f[r * STF_W + n + 1] = acc[mt][nt][half * 2 + 1];
                    }
            __syncthreads();

            const int j0 = np >> 2;          // first hidden unit of this pass
#pragma unroll
            for (int i = tid; i < 8192; i += 256) {
                int r  = i >> 6;             // row 0..127
                int jj = i & 63;             // unit within pass (64 units)
                int b  = m0 + r;
                int j  = j0 + jj;
                float4 a4 = *(const float4*)&stage_f[r * STF_W + jj * 4];
                float4 b4 = *(const float4*)(g_bias + np + jj * 4);

                float i_ = fsig(a4.x + b4.x);
                float f_ = fsig(a4.y + b4.y);
                float g_ = ftanh(a4.z + b4.z);
                float o_ = fsig(a4.w + b4.w);

                int idx = b * H_ + j;
                float c = f_ * g_c[idx] + i_ * g_;
                float h = o_ * ftanh(c);
                g_c[idx] = c;

                size_t oo = ((size_t)b * T_ + t) * H_ + j;
                out_hid[oo] = h;
                g_H[oo]     = __float2half_rn(h);
            }
            __syncthreads();
        }

        // ---- arrive after the step's second pass (wait is inside pass 0) ----
        if (t + 1 < T_) {
            if (tid == 0) {
                __threadfence();
                atomicAdd(&g_bar[grp], 1);
            }
            __syncthreads();
        }
    }
}

// ---------------------------------------------------------------------------
// probs GEMM: H @ Wgen^T, K=512 -> probs (+bg, n<97).  grid (1, 832), occ 2.
// ---------------------------------------------------------------------------
__global__ void __launch_bounds__(256, 2)
probs_kernel(const float* __restrict__ bias, float* __restrict__ outp)
{
    extern __shared__ char dsm[];

    const int tid = threadIdx.x;
    const int wid = tid >> 5;
    const int lid = tid & 31;
    const int wm  = wid & 1;
    const int wn  = wid >> 1;
    const int m0  = blockIdx.y * 128;

    uint32_t raw  = smem_u32(dsm);
    uint32_t base = (raw + 127) & ~127u;
    uint32_t stg[PNSTAGES];
#pragma unroll
    for (int s = 0; s < PNSTAGES; s++) stg[s] = base + s * PSTAGE;

    float acc[4][4][4];
#pragma unroll
    for (int mt = 0; mt < 4; mt++)
#pragma unroll
        for (int nt = 0; nt < 4; nt++)
#pragma unroll
            for (int r = 0; r < 4; r++) acc[mt][nt][r] = 0.0f;

    const int a_r  = lid & 15;
    const int a_kh = lid >> 4;
    const int b_r  = (lid & 7) + ((lid & 16) ? 8 : 0);
    const int b_kh = (lid >> 3) & 1;

    auto load_stage = [&](int ch, uint32_t sb) {
        const int k0 = ch * 64;
#pragma unroll
        for (int i = tid; i < 1024; i += 256) {
            int r = i >> 3, u = i & 7;
            uint32_t sw = (r << 7) + ((u ^ (r & 7)) << 4);
            cp16(sb + sw,         g_H  + (size_t)(m0 + r) * H_ + k0 + u * 8);
            cp16(sb + PTILE + sw, g_Wg + (size_t)r * H_ + k0 + u * 8);
        }
    };

    load_stage(0, stg[0]); cp_commit();
    load_stage(1, stg[1]); cp_commit();

    for (int ch = 0; ch < 8; ch++) {
        if (ch + 2 < 8) load_stage(ch + 2, stg[(ch + 2) % PNSTAGES]);
        cp_commit();
        cp_wait<2>();
        __syncthreads();

        const uint32_t aA = stg[ch % PNSTAGES];
        const uint32_t aB = aA + PTILE;
#pragma unroll
        for (int ks = 0; ks < 4; ks++) {
            uint32_t af[4][4], bf[2][4];
#pragma unroll
            for (int mt = 0; mt < 4; mt++) {
                int row = wm * 64 + mt * 16 + a_r;
                int kb  = ks * 2 + a_kh;
                ldmx4(af[mt], aA + (row << 7) + ((kb ^ (row & 7)) << 4));
            }
#pragma unroll
            for (int p = 0; p < 2; p++) {
                int row = wn * 32 + p * 16 + b_r;
                int kb  = ks * 2 + b_kh;
                ldmx4(bf[p], aB + (row << 7) + ((kb ^ (row & 7)) << 4));
            }
#pragma unroll
            for (int mt = 0; mt < 4; mt++)
#pragma unroll
                for (int nt = 0; nt < 4; nt++) {
                    int p = nt >> 1, o = (nt & 1) * 2;
                    mma_f16(acc[mt][nt], af[mt], bf[p][o], bf[p][o + 1]);
                }
        }
        __syncthreads();
    }

    const int qr = lid >> 2, qc = lid & 3;
#pragma unroll
    for (int mt = 0; mt < 4; mt++)
#pragma unroll
        for (int nt = 0; nt < 4; nt++)
#pragma unroll
            for (int half = 0; half < 2; half++) {
                int m = m0 + wm * 64 + mt * 16 + qr + half * 8;
                int n = wn * 32 + nt * 8 + qc * 2;
                float v0 = acc[mt][nt][half * 2];
                float v1 = acc[mt][nt][half * 2 + 1];
                if (n < NC_)     outp[(size_t)m * NC_ + n]     = v0 + bias[n];
                if (n + 1 < NC_) outp[(size_t)m * NC_ + n + 1] = v1 + bias[n + 1];
            }
}

// ---------------------------------------------------------------------------
// Launch: zero -> converts -> persistent recurrent (26 steps) -> probs
// d_out = [probs (B*T*97) | output_hiddens (B*T*512)]
// ---------------------------------------------------------------------------
extern "C" void kernel_launch(void* const* d_in, const int* in_sizes, int n_in,
                              void* d_out, int out_size)
{
    const float* bh   = (const float*)d_in[0];
    const int*   text = (const int*)  d_in[1];
    const float* emb  = (const float*)d_in[2];
    const float* Wih  = (const float*)d_in[3];
    const float* Whh  = (const float*)d_in[4];
    const float* bih  = (const float*)d_in[5];
    const float* bhh  = (const float*)d_in[6];
    const float* Wg   = (const float*)d_in[7];
    const float* bg   = (const float*)d_in[8];

    float* probs = (float*)d_out;                     // [M1, 97]
    float* hid   = probs + (size_t)M1_ * NC_;         // [M1, 512]

    (void)in_sizes; (void)n_in; (void)out_size;

    cudaFuncSetAttribute((const void*)recurrent_kernel,
                         cudaFuncAttributeMaxDynamicSharedMemorySize, SMEM_REC);
    cudaFuncSetAttribute((const void*)probs_kernel,
                         cudaFuncAttributeMaxDynamicSharedMemorySize, SMEM_PROBS);

    zero_state_kernel<<<(B_ * H_ / 4) / 256, 256>>>();
    convert_x_kernel<<<M1_, K1_ / 4>>>(bh, text, emb);
    convert_w_kernel<<<G_, KC_ / 4>>>(Whh, Wih);
    convert_wg_kernel<<<128, H_ / 4>>>(Wg);
    bias_kernel<<<8, 256>>>(bih, bhh);

    recurrent_kernel<<<GROUPS * GROUP_CTAS, 256, SMEM_REC>>>(hid);

    probs_kernel<<<dim3(1, 832), 256, SMEM_PROBS>>>(bg, probs);
}